// round 4
// baseline (speedup 1.0000x reference)
#include <cuda_runtime.h>

// Problem: B=4, D=64, K=32, N=8192. Total floats = 2,097,152 = 524288 float4.
#define Bk 4
#define Dk 64
#define Kk 32
#define GRID 592              // 4 CTAs * 148 SMs, all co-resident
#define TPB 256
#define NT 2048               // tiles; tile = 256 float4 = 1024 floats; tile>>3 = bd
#define MAXJ 4                // ceil(2048/592)

typedef unsigned long long u64;

__device__ unsigned g_count = 0;          // self-resetting barrier counter
__device__ float g_partial[NT];           // per-tile sum of E (deterministic)

__device__ __forceinline__ float ex2(float x) {
    float y; asm("ex2.approx.f32 %0, %1;" : "=f"(y) : "f"(x)); return y;
}
__device__ __forceinline__ u64 pk(float lo, float hi) {
    u64 r; asm("mov.b64 %0, {%1,%2};" : "=l"(r) : "f"(lo), "f"(hi)); return r;
}
__device__ __forceinline__ void upk(float& lo, float& hi, u64 v) {
    asm("mov.b64 {%0,%1}, %2;" : "=f"(lo), "=f"(hi) : "l"(v));
}
__device__ __forceinline__ u64 add2(u64 a, u64 b) {
    u64 r; asm("add.rn.f32x2 %0, %1, %2;" : "=l"(r) : "l"(a), "l"(b)); return r;
}
__device__ __forceinline__ u64 mul2(u64 a, u64 b) {
    u64 r; asm("mul.rn.f32x2 %0, %1, %2;" : "=l"(r) : "l"(a), "l"(b)); return r;
}
__device__ __forceinline__ u64 fma2(u64 a, u64 b, u64 c) {
    u64 r; asm("fma.rn.f32x2 %0, %1, %2, %3;" : "=l"(r) : "l"(a), "l"(b), "l"(c)); return r;
}

__global__ void __launch_bounds__(TPB, 4)
k_fused(const float* __restrict__ X, const float* __restrict__ cw,
        const float* __restrict__ sc, const float* __restrict__ fw,
        const float* __restrict__ fb, float* __restrict__ out)
{
    // Full per-(d,k) constant tables (exponent expanded):
    //   arg = slx*x^2 + p1*x + p0;  slx = scale*log2e, p1 = -2c*slx, p0 = c^2*slx
    __shared__ float2 s_pp[Dk][Kk];   // (p1, p0)       16 KB
    __shared__ float2 s_sn[Dk][Kk];   // (slx, -c)      16 KB
    __shared__ float  s_red[TPB / 32];
    __shared__ float  s_eg[Bk * Dk];
    __shared__ float  s_gamma[Bk * Dk];

    const int t   = threadIdx.x;
    const int blk = blockIdx.x;

    // ---- Prologue: build constant tables (coalesced over (k,d)) ----
    #pragma unroll
    for (int i = t; i < Dk * Kk; i += TPB) {
        const int k = i >> 6, d = i & 63;
        const float c   = cw[k * Dk + d];
        const float slx = sc[k * Dk + d] * 1.4426950408889634f;
        s_pp[d][k] = make_float2(-2.0f * c * slx, c * c * slx);
        s_sn[d][k] = make_float2(slx, -c);
    }
    __syncthreads();

    const float4* X4 = (const float4*)X;
    float4*       O4 = (float4*)out;

    u64 Eacc[MAXJ][2];   // E pairs kept in regs across the grid barrier
    int ntile = 0;

    // ---- Phase 1: cyclic tiles, packed f32x2 math ----
    #pragma unroll
    for (int j = 0; j < MAXJ; j++) {
        const int tile = blk + j * GRID;       // block-uniform
        if (tile < NT) {
            ntile = j + 1;
            const int d = (tile >> 3) & 63;
            const float4 v = X4[tile * (TPB) + t];
            u64 x2[2], xx2[2], den2[2], w2[2];
            x2[0] = pk(v.x, v.y);  x2[1] = pk(v.z, v.w);
            xx2[0] = mul2(x2[0], x2[0]);  xx2[1] = mul2(x2[1], x2[1]);
            den2[0] = den2[1] = 0ull;  w2[0] = w2[1] = 0ull;

            #pragma unroll 8
            for (int k = 0; k < Kk; k++) {
                const float2 pp = s_pp[d][k];
                const float2 sn = s_sn[d][k];
                const u64 p1 = pk(pp.x, pp.x), p0 = pk(pp.y, pp.y);
                const u64 sl = pk(sn.x, sn.x), nc = pk(sn.y, sn.y);
                #pragma unroll
                for (int p = 0; p < 2; p++) {
                    u64 a = fma2(p1, x2[p], p0);
                    a = fma2(sl, xx2[p], a);          // arg <= 0
                    float alo, ahi; upk(alo, ahi, a);
                    u64 e = pk(ex2(alo), ex2(ahi));
                    den2[p] = add2(den2[p], e);
                    w2[p]   = fma2(e, nc, w2[p]);     // w = sum e*(-c)
                }
            }

            float tsum;
            {
                u64 n0 = fma2(x2[0], den2[0], w2[0]); // num = x*den - sum(e*c)
                u64 n1 = fma2(x2[1], den2[1], w2[1]);
                float a0, a1, a2, a3, b0, b1, b2, b3;
                upk(a0, a1, n0); upk(a2, a3, n1);
                upk(b0, b1, den2[0]); upk(b2, b3, den2[1]);
                const float e0 = __fdividef(a0, b0), e1 = __fdividef(a1, b1);
                const float e2 = __fdividef(a2, b2), e3 = __fdividef(a3, b3);
                Eacc[j][0] = pk(e0, e1);
                Eacc[j][1] = pk(e2, e3);
                tsum = (e0 + e1) + (e2 + e3);
            }

            // block reduction -> g_partial[tile] (deterministic content)
            #pragma unroll
            for (int o = 16; o > 0; o >>= 1)
                tsum += __shfl_xor_sync(0xffffffffu, tsum, o);
            if ((t & 31) == 0) s_red[t >> 5] = tsum;
            __syncthreads();
            if (t == 0) {
                float s = 0.f;
                #pragma unroll
                for (int w = 0; w < TPB / 32; w++) s += s_red[w];
                g_partial[tile] = s;
            }
            __syncthreads();
        }
    }

    // ---- Grid barrier (self-resetting, graph-replayable) ----
    if (t == 0) {
        __threadfence();                       // publish g_partial
        atomicAdd(&g_count, 1u);
        while (*(volatile unsigned*)&g_count < (unsigned)GRID) __nanosleep(32);
        unsigned p2 = atomicAdd(&g_count, 1u);
        if (p2 == 2u * GRID - 1u) g_count = 0; // last block resets for replay
    }
    __syncthreads();
    __threadfence();

    // ---- Phase 2: E_glob and full (B,D) gamma table (redundant per block) ----
    {
        const float* gp = &g_partial[t << 3];  // t = b*64+d, 8 chunk-tiles each
        float s = 0.f;
        #pragma unroll
        for (int r = 0; r < 8; r++) s += __ldcg(gp + r);
        s_eg[t] = s * (1.0f / Kk);
    }
    __syncthreads();
    {
        const int b = t >> 6, i = t & 63;
        float acc = __ldg(fb + i);
        const float* fwr = fw + i * Dk;
        const float* eg  = s_eg + b * Dk;
        #pragma unroll 16
        for (int j = 0; j < Dk; j++) acc = fmaf(eg[j], __ldg(fwr + j), acc);
        s_gamma[t] = 1.f + 1.f / (1.f + __expf(-acc));   // 1 + sigmoid(b,d)
    }
    __syncthreads();

    // ---- Phase 3: scale register-resident E, single output write ----
    #pragma unroll
    for (int j = 0; j < MAXJ; j++) {
        const int tile = blk + j * GRID;
        if (j < ntile) {
            const float g = s_gamma[(tile >> 3) & 255];
            const u64 g2 = pk(g, g);
            u64 a = mul2(Eacc[j][0], g2);
            u64 b = mul2(Eacc[j][1], g2);
            float4 o;
            upk(o.x, o.y, a);
            upk(o.z, o.w, b);
            o.x = fmaxf(o.x, 0.f); o.y = fmaxf(o.y, 0.f);
            o.z = fmaxf(o.z, 0.f); o.w = fmaxf(o.w, 0.f);
            O4[tile * TPB + t] = o;
        }
    }
}

extern "C" void kernel_launch(void* const* d_in, const int* in_sizes, int n_in,
                              void* d_out, int out_size)
{
    const float* X   = (const float*)d_in[0];  // (B,D,T,H,W)
    const float* cw  = (const float*)d_in[1];  // (K,D)
    const float* sc  = (const float*)d_in[2];  // (K,D)
    const float* fcw = (const float*)d_in[3];  // (D,D)
    const float* fcb = (const float*)d_in[4];  // (D,)
    float* out = (float*)d_out;

    k_fused<<<GRID, TPB>>>(X, cw, sc, fcw, fcb, out);
}

// round 5
// speedup vs baseline: 2.4035x; 2.4035x over previous
#include <cuda_runtime.h>

// Problem: B=4, D=64, K=32, N=8192. Total floats = 2,097,152 = 524288 float4.
#define Kk 32
#define Dk 64
#define GRID 1024            // 8 CTAs/SM co-resident (capacity 148*8=1184)
#define TPB 128              // block handles 512 float4; thread handles 4

typedef unsigned long long u64;

__device__ unsigned g_count = 0;     // self-resetting grid-barrier counter
__device__ float g_partial[GRID];    // per-block sum of E (deterministic)

__device__ __forceinline__ float ex2(float x) {
    float y; asm("ex2.approx.f32 %0, %1;" : "=f"(y) : "f"(x)); return y;
}
__device__ __forceinline__ u64 pk(float lo, float hi) {
    u64 r; asm("mov.b64 %0, {%1,%2};" : "=l"(r) : "f"(lo), "f"(hi)); return r;
}
__device__ __forceinline__ void upk(float& lo, float& hi, u64 v) {
    asm("mov.b64 {%0,%1}, %2;" : "=f"(lo), "=f"(hi) : "l"(v));
}
__device__ __forceinline__ u64 add2(u64 a, u64 b) {
    u64 r; asm("add.rn.f32x2 %0, %1, %2;" : "=l"(r) : "l"(a), "l"(b)); return r;
}
__device__ __forceinline__ u64 mul2(u64 a, u64 b) {
    u64 r; asm("mul.rn.f32x2 %0, %1, %2;" : "=l"(r) : "l"(a), "l"(b)); return r;
}
__device__ __forceinline__ u64 fma2(u64 a, u64 b, u64 c) {
    u64 r; asm("fma.rn.f32x2 %0, %1, %2, %3;" : "=l"(r) : "l"(a), "l"(b), "l"(c)); return r;
}

__global__ void __launch_bounds__(TPB, 8)
k_fused(const float* __restrict__ X, const float* __restrict__ cw,
        const float* __restrict__ sc, const float* __restrict__ fw,
        const float* __restrict__ fb, float* __restrict__ out)
{
    // Per-k constants (d is block-uniform, compile-time smem addressing):
    //   arg = slx*x^2 + p1*x + p0;  slx = scale*log2e, p1 = -2c*slx, p0 = c^2*slx
    __shared__ u64 s_p1[Kk], s_p0[Kk], s_sl[Kk], s_nc[Kk];
    __shared__ float s_fw[Dk];
    __shared__ float s_red[TPB / 32];
    __shared__ float s_eg[Dk];
    __shared__ float s_fb;
    __shared__ float s_g1;          // 1 + gamma(b,d), block-uniform

    const int t   = threadIdx.x;
    const int blk = blockIdx.x;
    const int bd  = blk >> 2;       // blk = bd*4 + chunk
    const int d   = bd & 63;
    const int b   = bd >> 6;

    if (t < Kk) {
        const float c   = cw[t * Dk + d];
        const float slx = sc[t * Dk + d] * 1.4426950408889634f;
        const float p1  = -2.0f * c * slx;
        const float p0  = c * c * slx;
        s_p1[t] = pk(p1, p1);
        s_p0[t] = pk(p0, p0);
        s_sl[t] = pk(slx, slx);
        s_nc[t] = pk(-c, -c);
    }
    if (t >= 64 && t < 64 + Dk) s_fw[t - 64] = fw[d * Dk + (t - 64)];
    if (t == 63) s_fb = fb[d];
    __syncthreads();

    const float4* X4 = (const float4*)X;
    float4*       O4 = (float4*)out;

    // Load all 4 float4 up front (MLP=4), keep as packed pairs.
    u64 x2[8], Eacc[8];
    #pragma unroll
    for (int i = 0; i < 4; i++) {
        float4 v = X4[blk * 512 + i * TPB + t];
        x2[i * 2 + 0] = pk(v.x, v.y);
        x2[i * 2 + 1] = pk(v.z, v.w);
    }

    float ssum = 0.f;

    // ---- Phase 1: 4 groups of one float4 (2 packed pairs) ----
    #pragma unroll
    for (int i = 0; i < 4; i++) {
        const u64 xa = x2[i * 2 + 0], xb = x2[i * 2 + 1];
        const u64 xxa = mul2(xa, xa), xxb = mul2(xb, xb);
        u64 dena = 0ull, denb = 0ull, wa = 0ull, wb = 0ull;

        #pragma unroll 8
        for (int k = 0; k < Kk; k++) {
            const u64 p1 = s_p1[k], p0 = s_p0[k], sl = s_sl[k], nc = s_nc[k];
            u64 a0 = fma2(sl, xxa, fma2(p1, xa, p0));   // arg <= 0
            u64 a1 = fma2(sl, xxb, fma2(p1, xb, p0));
            float l0, h0, l1, h1;
            upk(l0, h0, a0);
            upk(l1, h1, a1);
            const u64 e0 = pk(ex2(l0), ex2(h0));
            const u64 e1 = pk(ex2(l1), ex2(h1));
            dena = add2(dena, e0);  wa = fma2(e0, nc, wa);   // w = sum e*(-c)
            denb = add2(denb, e1);  wb = fma2(e1, nc, wb);
        }

        const u64 na = fma2(xa, dena, wa);   // num = x*den - sum(e*c)
        const u64 nb = fma2(xb, denb, wb);
        float n0, n1, n2, n3, d0, d1, d2, d3;
        upk(n0, n1, na); upk(n2, n3, nb);
        upk(d0, d1, dena); upk(d2, d3, denb);
        const float e0 = __fdividef(n0, d0), e1 = __fdividef(n1, d1);
        const float e2 = __fdividef(n2, d2), e3 = __fdividef(n3, d3);
        Eacc[i * 2 + 0] = pk(e0, e1);
        Eacc[i * 2 + 1] = pk(e2, e3);
        ssum += (e0 + e1) + (e2 + e3);
    }

    // ---- Deterministic block reduction -> g_partial[blk] ----
    #pragma unroll
    for (int o = 16; o > 0; o >>= 1)
        ssum += __shfl_xor_sync(0xffffffffu, ssum, o);
    if ((t & 31) == 0) s_red[t >> 5] = ssum;
    __syncthreads();
    if (t == 0) {
        float s = 0.f;
        #pragma unroll
        for (int w = 0; w < TPB / 32; w++) s += s_red[w];
        g_partial[blk] = s;
    }

    // ---- Grid barrier (self-resetting, graph-replayable) ----
    if (t == 0) {
        __threadfence();                       // publish g_partial
        atomicAdd(&g_count, 1u);
        while (*(volatile unsigned*)&g_count < (unsigned)GRID) __nanosleep(32);
        unsigned p2 = atomicAdd(&g_count, 1u);
        if (p2 == 2u * GRID - 1u) g_count = 0; // last arrival resets for replay
    }
    __syncthreads();
    __threadfence();

    // ---- Phase 2: E_glob row b (64 values) and scalar gamma(b,d) ----
    if (t < Dk) {
        const float* gp = &g_partial[(b * Dk + t) * 4];
        float s = __ldcg(gp + 0) + __ldcg(gp + 1) + __ldcg(gp + 2) + __ldcg(gp + 3);
        s_eg[t] = s * (1.0f / Kk);
    }
    __syncthreads();
    if (t < 32) {
        float acc = s_eg[t] * s_fw[t] + s_eg[t + 32] * s_fw[t + 32];
        #pragma unroll
        for (int o = 16; o > 0; o >>= 1)
            acc += __shfl_xor_sync(0xffffffffu, acc, o);
        if (t == 0)
            s_g1 = 1.f + 1.f / (1.f + __expf(-(acc + s_fb)));  // 1 + sigmoid
    }
    __syncthreads();

    // ---- Phase 3: scale register-resident E, single output write ----
    const float g = s_g1;
    const u64 g2 = pk(g, g);
    #pragma unroll
    for (int i = 0; i < 4; i++) {
        u64 a = mul2(Eacc[i * 2 + 0], g2);
        u64 bq = mul2(Eacc[i * 2 + 1], g2);
        float4 o;
        upk(o.x, o.y, a);
        upk(o.z, o.w, bq);
        o.x = fmaxf(o.x, 0.f); o.y = fmaxf(o.y, 0.f);
        o.z = fmaxf(o.z, 0.f); o.w = fmaxf(o.w, 0.f);
        O4[blk * 512 + i * TPB + t] = o;
    }
}

extern "C" void kernel_launch(void* const* d_in, const int* in_sizes, int n_in,
                              void* d_out, int out_size)
{
    const float* X   = (const float*)d_in[0];  // (B,D,T,H,W)
    const float* cw  = (const float*)d_in[1];  // (K,D)
    const float* sc  = (const float*)d_in[2];  // (K,D)
    const float* fcw = (const float*)d_in[3];  // (D,D)
    const float* fcb = (const float*)d_in[4];  // (D,)
    float* out = (float*)d_out;

    k_fused<<<GRID, TPB>>>(X, cw, sc, fcw, fcb, out);
}

// round 6
// speedup vs baseline: 2.4061x; 1.0011x over previous
#include <cuda_runtime.h>

// Problem: B=4, D=64, K=32, N=8192. Total floats = 2,097,152 = 524288 float4.
#define Kk 32
#define Dk 64
#define GRID 1024            // 8 CTAs/SM co-resident (capacity 148*8=1184)
#define TPB 128              // block handles 512 float4; thread handles 4

typedef unsigned long long u64;

__device__ unsigned g_count = 0;     // self-resetting grid-barrier counter
__device__ float g_partial[GRID];    // per-block sum of E (deterministic)

__device__ __forceinline__ float ex2(float x) {
    float y; asm("ex2.approx.f32 %0, %1;" : "=f"(y) : "f"(x)); return y;
}
__device__ __forceinline__ u64 pk(float lo, float hi) {
    u64 r; asm("mov.b64 %0, {%1,%2};" : "=l"(r) : "f"(lo), "f"(hi)); return r;
}
__device__ __forceinline__ void upk(float& lo, float& hi, u64 v) {
    asm("mov.b64 {%0,%1}, %2;" : "=f"(lo), "=f"(hi) : "l"(v));
}
__device__ __forceinline__ u64 add2(u64 a, u64 b) {
    u64 r; asm("add.rn.f32x2 %0, %1, %2;" : "=l"(r) : "l"(a), "l"(b)); return r;
}
__device__ __forceinline__ u64 mul2(u64 a, u64 b) {
    u64 r; asm("mul.rn.f32x2 %0, %1, %2;" : "=l"(r) : "l"(a), "l"(b)); return r;
}
__device__ __forceinline__ u64 fma2(u64 a, u64 b, u64 c) {
    u64 r; asm("fma.rn.f32x2 %0, %1, %2, %3;" : "=l"(r) : "l"(a), "l"(b), "l"(c)); return r;
}

__global__ void __launch_bounds__(TPB, 8)
k_fused(const float* __restrict__ X, const float* __restrict__ cw,
        const float* __restrict__ sc, const float* __restrict__ fw,
        const float* __restrict__ fb, float* __restrict__ out)
{
    // Per-k constants (d is block-uniform, compile-time smem addressing):
    //   arg = slx*x^2 + p1*x + p0;  slx = scale*log2e, p1 = -2c*slx, p0 = c^2*slx
    __shared__ u64 s_p1[Kk], s_p0[Kk], s_sl[Kk], s_nc[Kk];
    __shared__ float s_fw[Dk];
    __shared__ float s_red[TPB / 32];
    __shared__ float s_eg[Dk];
    __shared__ float s_fb;
    __shared__ float s_g1;          // 1 + gamma(b,d), block-uniform

    const int t   = threadIdx.x;
    const int blk = blockIdx.x;
    const int bd  = blk >> 2;       // blk = bd*4 + chunk
    const int d   = bd & 63;
    const int b   = bd >> 6;

    if (t < Kk) {
        const float c   = cw[t * Dk + d];
        const float slx = sc[t * Dk + d] * 1.4426950408889634f;
        const float p1  = -2.0f * c * slx;
        const float p0  = c * c * slx;
        s_p1[t] = pk(p1, p1);
        s_p0[t] = pk(p0, p0);
        s_sl[t] = pk(slx, slx);
        s_nc[t] = pk(-c, -c);
    }
    if (t >= 64 && t < 64 + Dk) s_fw[t - 64] = fw[d * Dk + (t - 64)];
    if (t == 63) s_fb = fb[d];
    __syncthreads();

    const float4* X4 = (const float4*)X;
    float4*       O4 = (float4*)out;

    float ssum = 0.f;

    // ---- Phase 1: 4 groups of one float4 (2 packed pairs); E stored unscaled ----
    #pragma unroll
    for (int i = 0; i < 4; i++) {
        const float4 v = X4[blk * 512 + i * TPB + t];
        const u64 xa = pk(v.x, v.y), xb = pk(v.z, v.w);
        const u64 xxa = mul2(xa, xa), xxb = mul2(xb, xb);
        u64 dena = 0ull, denb = 0ull, wa = 0ull, wb = 0ull;

        #pragma unroll 8
        for (int k = 0; k < Kk; k++) {
            const u64 p1 = s_p1[k], p0 = s_p0[k], sl = s_sl[k], nc = s_nc[k];
            u64 a0 = fma2(sl, xxa, fma2(p1, xa, p0));   // arg <= 0
            u64 a1 = fma2(sl, xxb, fma2(p1, xb, p0));
            float l0, h0, l1, h1;
            upk(l0, h0, a0);
            upk(l1, h1, a1);
            const u64 e0 = pk(ex2(l0), ex2(h0));
            const u64 e1 = pk(ex2(l1), ex2(h1));
            dena = add2(dena, e0);  wa = fma2(e0, nc, wa);   // w = sum e*(-c)
            denb = add2(denb, e1);  wb = fma2(e1, nc, wb);
        }

        const u64 na = fma2(xa, dena, wa);   // num = x*den - sum(e*c)
        const u64 nb = fma2(xb, denb, wb);
        float n0, n1, n2, n3, d0, d1, d2, d3;
        upk(n0, n1, na); upk(n2, n3, nb);
        upk(d0, d1, dena); upk(d2, d3, denb);
        float4 o;
        o.x = __fdividef(n0, d0);
        o.y = __fdividef(n1, d1);
        o.z = __fdividef(n2, d2);
        o.w = __fdividef(n3, d3);
        ssum += (o.x + o.y) + (o.z + o.w);
        O4[blk * 512 + i * TPB + t] = o;     // unscaled E; rescaled post-barrier
    }

    // ---- Deterministic block reduction -> g_partial[blk] ----
    #pragma unroll
    for (int o = 16; o > 0; o >>= 1)
        ssum += __shfl_xor_sync(0xffffffffu, ssum, o);
    if ((t & 31) == 0) s_red[t >> 5] = ssum;
    __syncthreads();
    if (t == 0) {
        float s = 0.f;
        #pragma unroll
        for (int w = 0; w < TPB / 32; w++) s += s_red[w];
        g_partial[blk] = s;
    }

    // ---- Publish E stores + partials, then grid barrier (self-resetting) ----
    __threadfence();                 // every thread: make its E stores visible
    __syncthreads();
    if (t == 0) {
        atomicAdd(&g_count, 1u);
        while (*(volatile unsigned*)&g_count < (unsigned)GRID) __nanosleep(32);
        unsigned p2 = atomicAdd(&g_count, 1u);
        if (p2 == 2u * GRID - 1u) g_count = 0;  // last arrival resets for replay
    }
    __syncthreads();
    __threadfence();

    // ---- Phase 2: E_glob row b (64 values) and scalar gamma(b,d) ----
    if (t < Dk) {
        const float* gp = &g_partial[(b * Dk + t) * 4];
        float s = __ldcg(gp + 0) + __ldcg(gp + 1) + __ldcg(gp + 2) + __ldcg(gp + 3);
        s_eg[t] = s * (1.0f / Kk);
    }
    __syncthreads();
    if (t < 32) {
        float acc = s_eg[t] * s_fw[t] + s_eg[t + 32] * s_fw[t + 32];
        #pragma unroll
        for (int o = 16; o > 0; o >>= 1)
            acc += __shfl_xor_sync(0xffffffffu, acc, o);
        if (t == 0)
            s_g1 = 1.f + 1.f / (1.f + __expf(-(acc + s_fb)));  // 1 + sigmoid
    }
    __syncthreads();

    // ---- Phase 3: re-read E (L2-resident), scale, relu, final write ----
    const float g = s_g1;
    #pragma unroll
    for (int i = 0; i < 4; i++) {
        const float4* ip = O4 + blk * 512 + i * TPB + t;
        float4 o;
        o.x = __ldcg(&ip->x); o.y = __ldcg(&ip->y);
        o.z = __ldcg(&ip->z); o.w = __ldcg(&ip->w);
        o.x = fmaxf(o.x * g, 0.f); o.y = fmaxf(o.y * g, 0.f);
        o.z = fmaxf(o.z * g, 0.f); o.w = fmaxf(o.w * g, 0.f);
        O4[blk * 512 + i * TPB + t] = o;
    }
}

extern "C" void kernel_launch(void* const* d_in, const int* in_sizes, int n_in,
                              void* d_out, int out_size)
{
    const float* X   = (const float*)d_in[0];  // (B,D,T,H,W)
    const float* cw  = (const float*)d_in[1];  // (K,D)
    const float* sc  = (const float*)d_in[2];  // (K,D)
    const float* fcw = (const float*)d_in[3];  // (D,D)
    const float* fcb = (const float*)d_in[4];  // (D,)
    float* out = (float*)d_out;

    k_fused<<<GRID, TPB>>>(X, cw, sc, fcw, fcb, out);
}